// round 13
// baseline (speedup 1.0000x reference)
#include <cuda_runtime.h>
#include <cuda_fp16.h>
#include <cstdint>

#define Bb 2
#define Vv 4
#define Cc 64
#define Hh 256
#define Ww 256
#define Nn (Hh * Ww)       // 65536
#define BV (Bb * Vv)       // 8
#define EPSF 1e-8f
#define NSLICE 4
#define BVS 2              // bv per slice

// ---------------- scratch (device globals: allocation-free per harness rules) ----
__device__ __align__(16) __half g_featsTh[(size_t)BV * Nn * Cc]; // feats (BV,N,C) fp16  64MB
__device__ __align__(16) __half g_acch[(size_t)BV * Nn * Cc];    // accumulator fp16     64MB
__device__ float g_wz[(size_t)BV * Nn * 2];       // per-target (wsum, wz) fp32          4MB
__device__ float4 g_xyz[(size_t)BV * Nn];         // per-pixel {x, y, invz, Z}           8MB
// per-bv matrices (exact fp32): [Kinv(16), srcRTinv(16), dstRT(16), K(16)]
__device__ float g_mats[BV * 64];

// ---------------- streams/events (created at load time; no device allocations) ---
namespace {
struct StreamCtx {
    cudaStream_t sA, sB;       // A: splat chain, B: prep + normalize
    cudaEvent_t fork;
    cudaEvent_t eprep[NSLICE]; // B -> A: slice prep done
    cudaEvent_t esp[NSLICE];   // A -> B: slice splat done
    cudaEvent_t joinA, joinB;
    StreamCtx() {
        cudaStreamCreateWithFlags(&sA, cudaStreamNonBlocking);
        cudaStreamCreateWithFlags(&sB, cudaStreamNonBlocking);
        cudaEventCreateWithFlags(&fork, cudaEventDisableTiming);
        for (int i = 0; i < NSLICE; i++) {
            cudaEventCreateWithFlags(&eprep[i], cudaEventDisableTiming);
            cudaEventCreateWithFlags(&esp[i], cudaEventDisableTiming);
        }
        cudaEventCreateWithFlags(&joinA, cudaEventDisableTiming);
        cudaEventCreateWithFlags(&joinB, cudaEventDisableTiming);
    }
};
StreamCtx g_sc;
}

// Exact fp32 4x4 matvec, fma chain ascending j (matches XLA dot lowering order).
__device__ __forceinline__ void mv4(const float4* __restrict__ M,
                                    const float v[4], float o[4]) {
#pragma unroll
    for (int r = 0; r < 4; r++) {
        float4 m = __ldg(&M[r]);
        float s = __fmul_rn(m.x, v[0]);
        s = __fmaf_rn(m.y, v[1], s);
        s = __fmaf_rn(m.z, v[2], s);
        s = __fmaf_rn(m.w, v[3], s);
        o[r] = s;
    }
}

// ---------------- 4x4 inverse (Gauss-Jordan, partial pivot) ---------------------
__device__ void inv4(const float* a, float* o) {
    float m[4][8];
    for (int r = 0; r < 4; r++)
        for (int c = 0; c < 4; c++) {
            m[r][c] = a[r * 4 + c];
            m[r][4 + c] = (r == c) ? 1.f : 0.f;
        }
    for (int col = 0; col < 4; col++) {
        int piv = col;
        for (int r = col + 1; r < 4; r++)
            if (fabsf(m[r][col]) > fabsf(m[piv][col])) piv = r;
        if (piv != col)
            for (int c = 0; c < 8; c++) { float t = m[col][c]; m[col][c] = m[piv][c]; m[piv][c] = t; }
        float s = __fdiv_rn(1.f, m[col][col]);
        for (int c = 0; c < 8; c++) m[col][c] = __fmul_rn(m[col][c], s);
        for (int r = 0; r < 4; r++) {
            if (r == col) continue;
            float f = m[r][col];
            for (int c = 0; c < 8; c++) m[r][c] = __fmaf_rn(-f, m[col][c], m[r][c]);
        }
    }
    for (int r = 0; r < 4; r++)
        for (int c = 0; c < 4; c++) o[r * 4 + c] = m[r][4 + c];
}

__global__ void build_mats_kernel(const float* __restrict__ K,
                                  const float* __restrict__ srcRTinv,
                                  const float* __restrict__ dstRT) {
    int bv = threadIdx.x;
    if (bv >= BV) return;
    int b = bv / Vv;
    float Kb[16], Ki[16];
    for (int i = 0; i < 16; i++) Kb[i] = K[b * 16 + i];
    inv4(Kb, Ki);
    float* out = &g_mats[bv * 64];
    for (int i = 0; i < 16; i++) {
        out[i]      = Ki[i];
        out[16 + i] = srcRTinv[bv * 16 + i];
        out[32 + i] = dstRT[b * 16 + i];   // dst_RTs is (B,1,4,4)
        out[48 + i] = Kb[i];
    }
}

// ------- projection precompute (1 thread / pixel) + zero g_wz, per slice ---------
__global__ void __launch_bounds__(256) proj_kernel(const float* __restrict__ depths, int bv0) {
    int g = blockIdx.x * blockDim.x + threadIdx.x;   // [0, BVS*Nn)
    int w = (bv0 << 16) + g;
    int bv = w >> 16;
    int n = w & (Nn - 1);

    // fused: zero wz (one float2 per thread; keep resident — atomics land soon)
    reinterpret_cast<float2*>(g_wz)[w] = make_float2(0.f, 0.f);

    float gx = (float)(n & (Ww - 1));
    float gy = (float)(n >> 8);

    float d = __ldg(&depths[w]);
    const float* M = &g_mats[bv * 64];

    // Exact fp32 reference chain: xyp = K*(dstRT*(srcRTinv*(Kinv*proj)))
    float pr[4] = {__fmul_rn(gx, d), __fmul_rn(gy, d), d, 1.f};
    float cam[4], wld[4], c2[4], xyp[4];
    mv4((const float4*)(M + 0),  pr,  cam);
    mv4((const float4*)(M + 16), cam, wld);
    mv4((const float4*)(M + 32), wld, c2);
    mv4((const float4*)(M + 48), c2,  xyp);

    float Z = xyp[2];
    float zeps = __fadd_rn(Z, EPSF);
    float x = __fdiv_rn(xyp[0], zeps);     // reference: xyp0 / (z + eps)
    float y = __fdiv_rn(xyp[1], zeps);
    float invz = __frcp_rn(zeps);          // reference: 1.0 / (z + eps)
    g_xyz[w] = make_float4(x, y, invz, Z);
}

// ------- transpose feats (C,N)->(N,C) fp32->fp16 per slice + zero acch slice -----
// Streaming traffic uses evict-first (.cs) so the L2 stays owned by acch lines.
__global__ void transpose_kernel(const float* __restrict__ in, int bv0) {
    __shared__ float tile[32][33];
    int bv = bv0 + blockIdx.z;
    int c0 = blockIdx.y * 32;
    int n0 = blockIdx.x * 32;
    const float* ip = in + (size_t)bv * Cc * Nn;
    __half* op = g_featsTh + (size_t)bv * Nn * Cc;
    int tx = threadIdx.x, ty = threadIdx.y;

    // fused: zero this slice's acch (normal stores -> L2-resident for the splat)
    size_t zid = ((size_t)((blockIdx.z * gridDim.y + blockIdx.y) * gridDim.x + blockIdx.x)) * 256
                 + ty * 32 + tx;
    reinterpret_cast<uint2*>(g_acch + (size_t)bv0 * Nn * Cc)[zid] = make_uint2(0u, 0u);

#pragma unroll
    for (int i = 0; i < 32; i += 8)
        tile[ty + i][tx] = __ldcs(&ip[(size_t)(c0 + ty + i) * Nn + n0 + tx]);
    __syncthreads();
    // pack 2 halves and store with .cs (read-once downstream, evict-first)
    if (tx < 16) {
#pragma unroll
        for (int i = 0; i < 32; i += 8) {
            __half2 h = __floats2half2_rn(tile[2 * tx][ty + i], tile[2 * tx + 1][ty + i]);
            __stcs(reinterpret_cast<__half2*>(op + (size_t)(n0 + ty + i) * Cc + c0) + tx, h);
        }
    }
}

// ---------------- phase A: quadrant 4x4 grid, quarter-warp per tap, fp16 --------
// lane = qb*8 + sl: qb (0..3) = grid column, sl (0..7) = channel octet.
// Slot t = 4*i + qb -> jx = qb, jy = i: per-lane ddx^2 hoists out of the loop.
template <int QX, int QY, bool CHECK>
__device__ __forceinline__ void do_taps(float fx, float fy, float invz,
                                        __half* accp,
                                        __half2 h0, __half2 h1, __half2 h2, __half2 h3,
                                        int qb, float px0, float py0) {
    const float nhiz = __fmul_rn(invz, -0.5f);   // exact
    const int IDX0 = QX ? -1 : -2;
    const int IDY0 = QY ? -1 : -2;
    const int cdx = qb + IDX0;                   // loop-invariant column
    const float dxf = (float)cdx;
    const float ddx = dxf + fx;
    const float ddx2e = __fmaf_rn(ddx, ddx, EPSF);
    bool pxok = true;
    if (CHECK) {
        float px = px0 + dxf;
        pxok = (px >= 0.f) && (px < (float)Ww);
    }
#pragma unroll
    for (int i = 0; i < 4; i++) {
        float dyf = (float)(i + IDY0);
        float ddy = dyf + fy;
        float s2 = __fmaf_rn(ddy, ddy, ddx2e);
        float dist;
        asm("sqrt.approx.f32 %0, %1;" : "=f"(dist) : "f"(s2));
        // ws = (1 - dist/2) * invz, fused; sign(ws) == sign(1 - dist/2) since invz>0
        float ws = __fmaf_rn(dist, nhiz, invz);
        bool live = ws > 0.f;
        if (CHECK) {
            float py = py0 + dyf;
            live = live && pxok && (py >= 0.f) && (py < (float)Hh);
        }
        if (live) {
            __half2 wh = __float2half2_rn(ws);
            __half2 a0 = __hmul2(wh, h0);
            __half2 a1 = __hmul2(wh, h1);
            __half2 a2 = __hmul2(wh, h2);
            __half2 a3 = __hmul2(wh, h3);
            int off = (i + IDY0) * 256 + cdx;
            __half* p = accp + ((long)off << 6);
            asm volatile("red.global.add.noftz.v4.f16x2 [%0], {%1,%2,%3,%4};" ::
                         "l"(p),
                         "r"(*reinterpret_cast<const unsigned*>(&a0)),
                         "r"(*reinterpret_cast<const unsigned*>(&a1)),
                         "r"(*reinterpret_cast<const unsigned*>(&a2)),
                         "r"(*reinterpret_cast<const unsigned*>(&a3)) : "memory");
        }
    }
}

// ---------------- splat: one warp per source pixel, per slice --------------------
__global__ void __launch_bounds__(256, 8) splat_kernel(int bv0) {
    int w = (bv0 << 16) + (int)((blockIdx.x * blockDim.x + threadIdx.x) >> 5);
    int lane = threadIdx.x & 31;
    int bv = w >> 16;

    float4 pj = __ldcs(&g_xyz[w]);   // read-once, evict-first
    float Z = pj.w;
    if (!(Z > EPSF)) return;         // warp-uniform; ref adds w=0 -> no-op
    float x = pj.x, y = pj.y, invz = pj.z;
    float px0 = rintf(x);            // matches jnp.round (half-to-even)
    float py0 = rintf(y);

    float fx = px0 - x;              // feeds approx dist only
    float fy = py0 - y;
    int ix0 = (int)px0;              // exact: px0 integral
    int iy0 = (int)py0;
    long idx_base = (long)iy0 * Ww + ix0;

    bool qx = (fx <= 0.f);           // cx >= 0
    bool qy = (fy <= 0.f);
    float nhiz = __fmul_rn(invz, -0.5f);
    bool interior = (px0 >= 2.f) && (px0 <= (float)(Ww - 3)) &&
                    (py0 >= 2.f) && (py0 <= (float)(Hh - 3));

    // ---- phase B: one warp-wide v2 fp32 RED covers the 16-slot grid's (w, w*z).
    if (lane < 16) {
        int iqx0 = qx ? -1 : -2;
        int iqy0 = qy ? -1 : -2;
        int jx = lane & 3, jy = lane >> 2;
        float dxf = (float)(jx + iqx0);
        float dyf = (float)(jy + iqy0);
        int offt = (jy + iqy0) * 256 + jx + iqx0;
        float ddx = dxf + fx;
        float ddy = dyf + fy;
        float s2 = __fmaf_rn(ddx, ddx, __fmaf_rn(ddy, ddy, EPSF));
        float dist;
        asm("sqrt.approx.f32 %0, %1;" : "=f"(dist) : "f"(s2));
        float ws = __fmaf_rn(dist, nhiz, invz);   // identical value to phase A
        bool live = ws > 0.f;
        if (!interior) {
            float px = px0 + dxf;
            float py = py0 + dyf;
            live = live && (px >= 0.f) && (px < (float)Ww) &&
                           (py >= 0.f) && (py < (float)Hh);
        }
        if (live) {
            float* q = g_wz + (((long)bv << 17) + ((idx_base + offt) << 1));
            asm volatile("red.global.add.v2.f32 [%0], {%1,%2};" ::
                         "l"(q), "f"(ws), "f"(__fmul_rn(ws, Z)) : "memory");
        }
    }

    // ---- phase A: quarter-warp per tap; lane handles 8 channels (fp16x8).
    int qb = lane >> 3;          // grid column 0..3
    int sl = lane & 7;           // channel octet
    const uint4 fv = __ldcs(reinterpret_cast<const uint4*>(
        &g_featsTh[((size_t)w << 6) + 8 * sl]));
    __half2 h0 = *reinterpret_cast<const __half2*>(&fv.x);
    __half2 h1 = *reinterpret_cast<const __half2*>(&fv.y);
    __half2 h2 = *reinterpret_cast<const __half2*>(&fv.z);
    __half2 h3 = *reinterpret_cast<const __half2*>(&fv.w);
    __half* accp = g_acch + ((((long)bv << 16) + idx_base) << 6) + 8 * sl;

    if (interior) {
        if (qx) { if (qy) do_taps<1,1,false>(fx,fy,invz,accp,h0,h1,h2,h3,qb,px0,py0);
                  else    do_taps<1,0,false>(fx,fy,invz,accp,h0,h1,h2,h3,qb,px0,py0); }
        else    { if (qy) do_taps<0,1,false>(fx,fy,invz,accp,h0,h1,h2,h3,qb,px0,py0);
                  else    do_taps<0,0,false>(fx,fy,invz,accp,h0,h1,h2,h3,qb,px0,py0); }
    } else {
        if (qx) { if (qy) do_taps<1,1,true>(fx,fy,invz,accp,h0,h1,h2,h3,qb,px0,py0);
                  else    do_taps<1,0,true>(fx,fy,invz,accp,h0,h1,h2,h3,qb,px0,py0); }
        else    { if (qy) do_taps<0,1,true>(fx,fy,invz,accp,h0,h1,h2,h3,qb,px0,py0);
                  else    do_taps<0,0,true>(fx,fy,invz,accp,h0,h1,h2,h3,qb,px0,py0); }
    }
}

// ---------------- normalize: 64-px tiles, fp16 acc read, rcp+mul, .cs out --------
__global__ void __launch_bounds__(256) normalize_kernel(float* __restrict__ out, int bv0) {
    __shared__ float tile[64][65];   // [channel][pixel]
    __shared__ float rws[64];
    __shared__ float zss[64];
    int bv = bv0 + blockIdx.y;
    int n0 = blockIdx.x * 64;
    int tid = threadIdx.x;

    const uint4* acc16 = reinterpret_cast<const uint4*>(
        g_acch + (((size_t)bv * Nn + n0) << 6));
#pragma unroll
    for (int r = 0; r < 2; r++) {
        int idx = r * 256 + tid;     // [0, 512): 8 uint4 per pixel
        int p = idx >> 3;            // pixel 0..63
        int q8 = idx & 7;            // channel octet
        uint4 v = acc16[idx];
        const __half2* hp = reinterpret_cast<const __half2*>(&v);
#pragma unroll
        for (int k = 0; k < 4; k++) {
            float2 f2 = __half22float2(hp[k]);
            tile[8 * q8 + 2 * k + 0][p] = f2.x;
            tile[8 * q8 + 2 * k + 1][p] = f2.y;
        }
    }
    if (tid < 64) {
        float2 wzv = reinterpret_cast<const float2*>(g_wz)[(size_t)bv * Nn + n0 + tid];
        rws[tid] = __frcp_rn(__fadd_rn(wzv.x, EPSF));  // rcp+mul vs div: <=2ulp
        zss[tid] = wzv.y;
    }
    __syncthreads();

    float* ob = out + (size_t)bv * (Cc + 1) * Nn + n0;
#pragma unroll
    for (int r = 0; r < 4; r++) {
        int idx = r * 256 + tid;
        int c = idx >> 4;            // channel 0..63
        int j = idx & 15;            // pixel quad
        float4 o;
        o.x = __fmul_rn(tile[c][4 * j + 0], rws[4 * j + 0]);
        o.y = __fmul_rn(tile[c][4 * j + 1], rws[4 * j + 1]);
        o.z = __fmul_rn(tile[c][4 * j + 2], rws[4 * j + 2]);
        o.w = __fmul_rn(tile[c][4 * j + 3], rws[4 * j + 3]);
        __stcs(reinterpret_cast<float4*>(ob + (size_t)c * Nn) + j, o);
    }
    if (tid < 16) {
        int j = tid;
        float4 o;
        o.x = __fmul_rn(zss[4 * j + 0], rws[4 * j + 0]);
        o.y = __fmul_rn(zss[4 * j + 1], rws[4 * j + 1]);
        o.z = __fmul_rn(zss[4 * j + 2], rws[4 * j + 2]);
        o.w = __fmul_rn(zss[4 * j + 3], rws[4 * j + 3]);
        __stcs(reinterpret_cast<float4*>(ob + (size_t)Cc * Nn) + j, o);
    }
}

// ------- launch: stream A = splat chain; stream B = prep + normalize -------------
extern "C" void kernel_launch(void* const* d_in, const int* in_sizes, int n_in,
                              void* d_out, int out_size) {
    const float* feats    = (const float*)d_in[0];
    const float* depths   = (const float*)d_in[1];
    const float* K        = (const float*)d_in[2];
    const float* srcRTinv = (const float*)d_in[4];
    const float* dstRT    = (const float*)d_in[5];
    float* out = (float*)d_out;

    build_mats_kernel<<<1, 32>>>(K, srcRTinv, dstRT);   // capture-origin stream
    cudaEventRecord(g_sc.fork, 0);
    cudaStreamWaitEvent(g_sc.sA, g_sc.fork, 0);
    cudaStreamWaitEvent(g_sc.sB, g_sc.fork, 0);

    // B: all slice preps up front (runs ahead of / under the splat chain)
    for (int s = 0; s < NSLICE; s++) {
        int bv0 = s * BVS;
        proj_kernel<<<(BVS * Nn) / 256, 256, 0, g_sc.sB>>>(depths, bv0);
        transpose_kernel<<<dim3(Nn / 32, Cc / 32, BVS), dim3(32, 8), 0, g_sc.sB>>>(feats, bv0);
        cudaEventRecord(g_sc.eprep[s], g_sc.sB);
    }
    // A: splats back-to-back, each gated only on its slice's prep
    for (int s = 0; s < NSLICE; s++) {
        cudaStreamWaitEvent(g_sc.sA, g_sc.eprep[s], 0);
        splat_kernel<<<(BVS * Nn * 32) / 256, 256, 0, g_sc.sA>>>(s * BVS);
        cudaEventRecord(g_sc.esp[s], g_sc.sA);
    }
    // B: normalizes, each gated on its slice's splat
    for (int s = 0; s < NSLICE; s++) {
        cudaStreamWaitEvent(g_sc.sB, g_sc.esp[s], 0);
        normalize_kernel<<<dim3(Nn / 64, BVS), 256, 0, g_sc.sB>>>(out, s * BVS);
    }

    cudaEventRecord(g_sc.joinA, g_sc.sA);
    cudaEventRecord(g_sc.joinB, g_sc.sB);
    cudaStreamWaitEvent(0, g_sc.joinA, 0);
    cudaStreamWaitEvent(0, g_sc.joinB, 0);
}

// round 15
// speedup vs baseline: 1.0367x; 1.0367x over previous
#include <cuda_runtime.h>
#include <cuda_fp16.h>
#include <cstdint>

#define Bb 2
#define Vv 4
#define Cc 64
#define Hh 256
#define Ww 256
#define Nn (Hh * Ww)       // 65536
#define BV (Bb * Vv)       // 8
#define EPSF 1e-8f

// ---------------- scratch (device globals: allocation-free per harness rules) ----
__device__ __align__(16) __half g_featsTh[(size_t)BV * Nn * Cc]; // feats (BV,N,C) fp16  64MB
__device__ __align__(16) __half g_acch[(size_t)BV * Nn * Cc];    // accumulator fp16     64MB
__device__ float g_wz[(size_t)BV * Nn * 2];       // per-target (wsum, wz) fp32          4MB
__device__ float4 g_xyz[(size_t)BV * Nn];         // per-pixel {x, y, invz, Z}           8MB
// per-bv matrices (exact fp32): [Kinv(16), srcRTinv(16), dstRT(16), K(16)]
__device__ float g_mats[BV * 64];

// Exact fp32 4x4 matvec, fma chain ascending j (matches XLA dot lowering order).
__device__ __forceinline__ void mv4(const float4* __restrict__ M,
                                    const float v[4], float o[4]) {
#pragma unroll
    for (int r = 0; r < 4; r++) {
        float4 m = __ldg(&M[r]);
        float s = __fmul_rn(m.x, v[0]);
        s = __fmaf_rn(m.y, v[1], s);
        s = __fmaf_rn(m.z, v[2], s);
        s = __fmaf_rn(m.w, v[3], s);
        o[r] = s;
    }
}

// ---------------- 4x4 inverse (Gauss-Jordan, partial pivot) ---------------------
__device__ void inv4(const float* a, float* o) {
    float m[4][8];
    for (int r = 0; r < 4; r++)
        for (int c = 0; c < 4; c++) {
            m[r][c] = a[r * 4 + c];
            m[r][4 + c] = (r == c) ? 1.f : 0.f;
        }
    for (int col = 0; col < 4; col++) {
        int piv = col;
        for (int r = col + 1; r < 4; r++)
            if (fabsf(m[r][col]) > fabsf(m[piv][col])) piv = r;
        if (piv != col)
            for (int c = 0; c < 8; c++) { float t = m[col][c]; m[col][c] = m[piv][c]; m[piv][c] = t; }
        float s = __fdiv_rn(1.f, m[col][col]);
        for (int c = 0; c < 8; c++) m[col][c] = __fmul_rn(m[col][c], s);
        for (int r = 0; r < 4; r++) {
            if (r == col) continue;
            float f = m[r][col];
            for (int c = 0; c < 8; c++) m[r][c] = __fmaf_rn(-f, m[col][c], m[r][c]);
        }
    }
    for (int r = 0; r < 4; r++)
        for (int c = 0; c < 4; c++) o[r * 4 + c] = m[r][4 + c];
}

__global__ void build_mats_kernel(const float* __restrict__ K,
                                  const float* __restrict__ srcRTinv,
                                  const float* __restrict__ dstRT) {
    int bv = threadIdx.x;
    if (bv >= BV) return;
    int b = bv / Vv;
    float Kb[16], Ki[16];
    for (int i = 0; i < 16; i++) Kb[i] = K[b * 16 + i];
    inv4(Kb, Ki);
    float* out = &g_mats[bv * 64];
    for (int i = 0; i < 16; i++) {
        out[i]      = Ki[i];
        out[16 + i] = srcRTinv[bv * 16 + i];
        out[32 + i] = dstRT[b * 16 + i];   // dst_RTs is (B,1,4,4)
        out[48 + i] = Kb[i];
    }
}

// ------- projection precompute (1 thread / pixel) + zero g_wz --------------------
__global__ void __launch_bounds__(256) proj_kernel(const float* __restrict__ depths) {
    int w = blockIdx.x * blockDim.x + threadIdx.x;   // BV*Nn threads
    int bv = w >> 16;
    int n = w & (Nn - 1);

    // fused: zero wz (one float2 per thread)
    reinterpret_cast<float2*>(g_wz)[w] = make_float2(0.f, 0.f);

    float gx = (float)(n & (Ww - 1));
    float gy = (float)(n >> 8);

    float d = __ldcs(&depths[w]);    // read-once
    const float* M = &g_mats[bv * 64];

    // Exact fp32 reference chain: xyp = K*(dstRT*(srcRTinv*(Kinv*proj)))
    float pr[4] = {__fmul_rn(gx, d), __fmul_rn(gy, d), d, 1.f};
    float cam[4], wld[4], c2[4], xyp[4];
    mv4((const float4*)(M + 0),  pr,  cam);
    mv4((const float4*)(M + 16), cam, wld);
    mv4((const float4*)(M + 32), wld, c2);
    mv4((const float4*)(M + 48), c2,  xyp);

    float Z = xyp[2];
    float zeps = __fadd_rn(Z, EPSF);
    float x = __fdiv_rn(xyp[0], zeps);     // reference: xyp0 / (z + eps)
    float y = __fdiv_rn(xyp[1], zeps);
    float invz = __frcp_rn(zeps);          // reference: 1.0 / (z + eps)
    g_xyz[w] = make_float4(x, y, invz, Z);
}

// ------- transpose feats (C,N)->(N,C) fp32->fp16, fused zero of g_acch -----------
__global__ void transpose_kernel(const float* __restrict__ in) {
    __shared__ float tile[32][33];
    int bv = blockIdx.z;
    int c0 = blockIdx.y * 32;
    int n0 = blockIdx.x * 32;
    const float* ip = in + (size_t)bv * Cc * Nn;
    __half* op = g_featsTh + (size_t)bv * Nn * Cc;
    int tx = threadIdx.x, ty = threadIdx.y;

    // fused: zero acc (1 uint2/thread; 32768 blocks x 256 thr = exactly 64MB/8B)
    size_t zid = ((size_t)((blockIdx.z * gridDim.y + blockIdx.y) * gridDim.x + blockIdx.x)) * 256
                 + ty * 32 + tx;
    reinterpret_cast<uint2*>(g_acch)[zid] = make_uint2(0u, 0u);

#pragma unroll
    for (int i = 0; i < 32; i += 8)
        tile[ty + i][tx] = __ldcs(&ip[(size_t)(c0 + ty + i) * Nn + n0 + tx]);
    __syncthreads();
    // pack 2 halves and store with .cs (read-once downstream, evict-first)
    if (tx < 16) {
#pragma unroll
        for (int i = 0; i < 32; i += 8) {
            __half2 h = __floats2half2_rn(tile[2 * tx][ty + i], tile[2 * tx + 1][ty + i]);
            __stcs(reinterpret_cast<__half2*>(op + (size_t)(n0 + ty + i) * Cc + c0) + tx, h);
        }
    }
}

// ---------------- phase A: quadrant 4x4 grid, quarter-warp per tap, fp16 --------
// lane = qb*8 + sl: qb (0..3) = grid column, sl (0..7) = channel octet.
// Slot t = 4*i + qb -> jx = qb, jy = i: per-lane ddx^2 hoists out of the loop.
template <int QX, int QY, bool CHECK>
__device__ __forceinline__ void do_taps(float fx, float fy, float invz,
                                        __half* accp,
                                        __half2 h0, __half2 h1, __half2 h2, __half2 h3,
                                        int qb, float px0, float py0) {
    const float nhiz = __fmul_rn(invz, -0.5f);   // exact
    const int IDX0 = QX ? -1 : -2;
    const int IDY0 = QY ? -1 : -2;
    const int cdx = qb + IDX0;                   // loop-invariant column
    const float dxf = (float)cdx;
    const float ddx = dxf + fx;
    const float ddx2e = __fmaf_rn(ddx, ddx, EPSF);
    bool pxok = true;
    if (CHECK) {
        float px = px0 + dxf;
        pxok = (px >= 0.f) && (px < (float)Ww);
    }
#pragma unroll
    for (int i = 0; i < 4; i++) {
        float dyf = (float)(i + IDY0);
        float ddy = dyf + fy;
        float s2 = __fmaf_rn(ddy, ddy, ddx2e);
        float dist;
        asm("sqrt.approx.f32 %0, %1;" : "=f"(dist) : "f"(s2));
        // ws = (1 - dist/2) * invz, fused; sign(ws) == sign(1 - dist/2) since invz>0
        float ws = __fmaf_rn(dist, nhiz, invz);
        bool live = ws > 0.f;
        if (CHECK) {
            float py = py0 + dyf;
            live = live && pxok && (py >= 0.f) && (py < (float)Hh);
        }
        if (live) {
            __half2 wh = __float2half2_rn(ws);
            __half2 a0 = __hmul2(wh, h0);
            __half2 a1 = __hmul2(wh, h1);
            __half2 a2 = __hmul2(wh, h2);
            __half2 a3 = __hmul2(wh, h3);
            int off = (i + IDY0) * 256 + cdx;
            __half* p = accp + ((long)off << 6);
            asm volatile("red.global.add.noftz.v4.f16x2 [%0], {%1,%2,%3,%4};" ::
                         "l"(p),
                         "r"(*reinterpret_cast<const unsigned*>(&a0)),
                         "r"(*reinterpret_cast<const unsigned*>(&a1)),
                         "r"(*reinterpret_cast<const unsigned*>(&a2)),
                         "r"(*reinterpret_cast<const unsigned*>(&a3)) : "memory");
        }
    }
}

// ---------------- splat: one warp per source pixel -------------------------------
__global__ void __launch_bounds__(256, 8) splat_kernel() {
    int w = (int)((blockIdx.x * blockDim.x + threadIdx.x) >> 5);
    int lane = threadIdx.x & 31;
    int bv = w >> 16;

    float4 pj = __ldcs(&g_xyz[w]);   // read-once, evict-first
    float Z = pj.w;
    if (!(Z > EPSF)) return;         // warp-uniform; ref adds w=0 -> no-op
    float x = pj.x, y = pj.y, invz = pj.z;
    float px0 = rintf(x);            // matches jnp.round (half-to-even)
    float py0 = rintf(y);

    float fx = px0 - x;              // feeds approx dist only
    float fy = py0 - y;
    int ix0 = (int)px0;              // exact: px0 integral
    int iy0 = (int)py0;
    long idx_base = (long)iy0 * Ww + ix0;

    bool qx = (fx <= 0.f);           // cx >= 0
    bool qy = (fy <= 0.f);
    float nhiz = __fmul_rn(invz, -0.5f);
    bool interior = (px0 >= 2.f) && (px0 <= (float)(Ww - 3)) &&
                    (py0 >= 2.f) && (py0 <= (float)(Hh - 3));

    // ---- phase B: one warp-wide v2 fp32 RED covers the 16-slot grid's (w, w*z).
    if (lane < 16) {
        int iqx0 = qx ? -1 : -2;
        int iqy0 = qy ? -1 : -2;
        int jx = lane & 3, jy = lane >> 2;
        float dxf = (float)(jx + iqx0);
        float dyf = (float)(jy + iqy0);
        int offt = (jy + iqy0) * 256 + jx + iqx0;
        float ddx = dxf + fx;
        float ddy = dyf + fy;
        float s2 = __fmaf_rn(ddx, ddx, __fmaf_rn(ddy, ddy, EPSF));
        float dist;
        asm("sqrt.approx.f32 %0, %1;" : "=f"(dist) : "f"(s2));
        float ws = __fmaf_rn(dist, nhiz, invz);   // identical value to phase A
        bool live = ws > 0.f;
        if (!interior) {
            float px = px0 + dxf;
            float py = py0 + dyf;
            live = live && (px >= 0.f) && (px < (float)Ww) &&
                           (py >= 0.f) && (py < (float)Hh);
        }
        if (live) {
            float* q = g_wz + (((long)bv << 17) + ((idx_base + offt) << 1));
            asm volatile("red.global.add.v2.f32 [%0], {%1,%2};" ::
                         "l"(q), "f"(ws), "f"(__fmul_rn(ws, Z)) : "memory");
        }
    }

    // ---- phase A: quarter-warp per tap; lane handles 8 channels (fp16x8).
    int qb = lane >> 3;          // grid column 0..3
    int sl = lane & 7;           // channel octet
    const uint4 fv = __ldcs(reinterpret_cast<const uint4*>(
        &g_featsTh[((size_t)w << 6) + 8 * sl]));
    __half2 h0 = *reinterpret_cast<const __half2*>(&fv.x);
    __half2 h1 = *reinterpret_cast<const __half2*>(&fv.y);
    __half2 h2 = *reinterpret_cast<const __half2*>(&fv.z);
    __half2 h3 = *reinterpret_cast<const __half2*>(&fv.w);
    __half* accp = g_acch + ((((long)bv << 16) + idx_base) << 6) + 8 * sl;

    if (interior) {
        if (qx) { if (qy) do_taps<1,1,false>(fx,fy,invz,accp,h0,h1,h2,h3,qb,px0,py0);
                  else    do_taps<1,0,false>(fx,fy,invz,accp,h0,h1,h2,h3,qb,px0,py0); }
        else    { if (qy) do_taps<0,1,false>(fx,fy,invz,accp,h0,h1,h2,h3,qb,px0,py0);
                  else    do_taps<0,0,false>(fx,fy,invz,accp,h0,h1,h2,h3,qb,px0,py0); }
    } else {
        if (qx) { if (qy) do_taps<1,1,true>(fx,fy,invz,accp,h0,h1,h2,h3,qb,px0,py0);
                  else    do_taps<1,0,true>(fx,fy,invz,accp,h0,h1,h2,h3,qb,px0,py0); }
        else    { if (qy) do_taps<0,1,true>(fx,fy,invz,accp,h0,h1,h2,h3,qb,px0,py0);
                  else    do_taps<0,0,true>(fx,fy,invz,accp,h0,h1,h2,h3,qb,px0,py0); }
    }
}

// ---------------- normalize: 64-px tiles, fp16 acc read, rcp+mul, .cs out --------
__global__ void __launch_bounds__(256) normalize_kernel(float* __restrict__ out) {
    __shared__ float tile[64][65];   // [channel][pixel]
    __shared__ float rws[64];
    __shared__ float zss[64];
    int bv = blockIdx.y;
    int n0 = blockIdx.x * 64;
    int tid = threadIdx.x;

    const uint4* acc16 = reinterpret_cast<const uint4*>(
        g_acch + (((size_t)bv * Nn + n0) << 6));
#pragma unroll
    for (int r = 0; r < 2; r++) {
        int idx = r * 256 + tid;     // [0, 512): 8 uint4 per pixel
        int p = idx >> 3;            // pixel 0..63
        int q8 = idx & 7;            // channel octet
        uint4 v = acc16[idx];
        const __half2* hp = reinterpret_cast<const __half2*>(&v);
#pragma unroll
        for (int k = 0; k < 4; k++) {
            float2 f2 = __half22float2(hp[k]);
            tile[8 * q8 + 2 * k + 0][p] = f2.x;
            tile[8 * q8 + 2 * k + 1][p] = f2.y;
        }
    }
    if (tid < 64) {
        float2 wzv = reinterpret_cast<const float2*>(g_wz)[(size_t)bv * Nn + n0 + tid];
        rws[tid] = __frcp_rn(__fadd_rn(wzv.x, EPSF));  // rcp+mul vs div: <=2ulp
        zss[tid] = wzv.y;
    }
    __syncthreads();

    float* ob = out + (size_t)bv * (Cc + 1) * Nn + n0;
#pragma unroll
    for (int r = 0; r < 4; r++) {
        int idx = r * 256 + tid;
        int c = idx >> 4;            // channel 0..63
        int j = idx & 15;            // pixel quad
        float4 o;
        o.x = __fmul_rn(tile[c][4 * j + 0], rws[4 * j + 0]);
        o.y = __fmul_rn(tile[c][4 * j + 1], rws[4 * j + 1]);
        o.z = __fmul_rn(tile[c][4 * j + 2], rws[4 * j + 2]);
        o.w = __fmul_rn(tile[c][4 * j + 3], rws[4 * j + 3]);
        __stcs(reinterpret_cast<float4*>(ob + (size_t)c * Nn) + j, o);
    }
    if (tid < 16) {
        int j = tid;
        float4 o;
        o.x = __fmul_rn(zss[4 * j + 0], rws[4 * j + 0]);
        o.y = __fmul_rn(zss[4 * j + 1], rws[4 * j + 1]);
        o.z = __fmul_rn(zss[4 * j + 2], rws[4 * j + 2]);
        o.w = __fmul_rn(zss[4 * j + 3], rws[4 * j + 3]);
        __stcs(reinterpret_cast<float4*>(ob + (size_t)Cc * Nn) + j, o);
    }
}

// ---------------- launch: serial (LTS is shared; overlap conserves bytes) --------
extern "C" void kernel_launch(void* const* d_in, const int* in_sizes, int n_in,
                              void* d_out, int out_size) {
    const float* feats    = (const float*)d_in[0];
    const float* depths   = (const float*)d_in[1];
    const float* K        = (const float*)d_in[2];
    const float* srcRTinv = (const float*)d_in[4];
    const float* dstRT    = (const float*)d_in[5];
    float* out = (float*)d_out;

    build_mats_kernel<<<1, 32>>>(K, srcRTinv, dstRT);
    proj_kernel<<<(BV * Nn) / 256, 256>>>(depths);                        // + zeroes g_wz
    transpose_kernel<<<dim3(Nn / 32, Cc / 32, BV), dim3(32, 8)>>>(feats); // + zeroes g_acch
    splat_kernel<<<(BV * Nn * 32) / 256, 256>>>();
    normalize_kernel<<<dim3(Nn / 64, BV), 256>>>(out);
}

// round 16
// speedup vs baseline: 1.1653x; 1.1241x over previous
#include <cuda_runtime.h>
#include <cuda_fp16.h>
#include <cstdint>

#define Bb 2
#define Vv 4
#define Cc 64
#define Hh 256
#define Ww 256
#define Nn (Hh * Ww)       // 65536
#define BV (Bb * Vv)       // 8
#define EPSF 1e-8f

// ---------------- scratch (device globals: allocation-free per harness rules) ----
__device__ __align__(16) __half g_acch[(size_t)BV * Nn * Cc];    // accumulator fp16  64MB
__device__ float g_wz[(size_t)BV * Nn * 2];       // per-target (wsum, wz) fp32        4MB
__device__ float4 g_xyz[(size_t)BV * Nn];         // per-pixel {x, y, invz, Z}         8MB
// per-bv matrices (exact fp32): [Kinv(16), srcRTinv(16), dstRT(16), K(16)]
__device__ float g_mats[BV * 64];

// Exact fp32 4x4 matvec, fma chain ascending j (matches XLA dot lowering order).
__device__ __forceinline__ void mv4(const float4* __restrict__ M,
                                    const float v[4], float o[4]) {
#pragma unroll
    for (int r = 0; r < 4; r++) {
        float4 m = __ldg(&M[r]);
        float s = __fmul_rn(m.x, v[0]);
        s = __fmaf_rn(m.y, v[1], s);
        s = __fmaf_rn(m.z, v[2], s);
        s = __fmaf_rn(m.w, v[3], s);
        o[r] = s;
    }
}

// ---------------- 4x4 inverse (Gauss-Jordan, partial pivot) ---------------------
__device__ void inv4(const float* a, float* o) {
    float m[4][8];
    for (int r = 0; r < 4; r++)
        for (int c = 0; c < 4; c++) {
            m[r][c] = a[r * 4 + c];
            m[r][4 + c] = (r == c) ? 1.f : 0.f;
        }
    for (int col = 0; col < 4; col++) {
        int piv = col;
        for (int r = col + 1; r < 4; r++)
            if (fabsf(m[r][col]) > fabsf(m[piv][col])) piv = r;
        if (piv != col)
            for (int c = 0; c < 8; c++) { float t = m[col][c]; m[col][c] = m[piv][c]; m[piv][c] = t; }
        float s = __fdiv_rn(1.f, m[col][col]);
        for (int c = 0; c < 8; c++) m[col][c] = __fmul_rn(m[col][c], s);
        for (int r = 0; r < 4; r++) {
            if (r == col) continue;
            float f = m[r][col];
            for (int c = 0; c < 8; c++) m[r][c] = __fmaf_rn(-f, m[col][c], m[r][c]);
        }
    }
    for (int r = 0; r < 4; r++)
        for (int c = 0; c < 4; c++) o[r * 4 + c] = m[r][4 + c];
}

__global__ void build_mats_kernel(const float* __restrict__ K,
                                  const float* __restrict__ srcRTinv,
                                  const float* __restrict__ dstRT) {
    int bv = threadIdx.x;
    if (bv >= BV) return;
    int b = bv / Vv;
    float Kb[16], Ki[16];
    for (int i = 0; i < 16; i++) Kb[i] = K[b * 16 + i];
    inv4(Kb, Ki);
    float* out = &g_mats[bv * 64];
    for (int i = 0; i < 16; i++) {
        out[i]      = Ki[i];
        out[16 + i] = srcRTinv[bv * 16 + i];
        out[32 + i] = dstRT[b * 16 + i];   // dst_RTs is (B,1,4,4)
        out[48 + i] = Kb[i];
    }
}

// ------- projection precompute (1 thread / pixel) + zero g_wz + zero g_acch ------
__global__ void __launch_bounds__(256) proj_kernel(const float* __restrict__ depths) {
    int w = blockIdx.x * blockDim.x + threadIdx.x;   // BV*Nn threads
    int bv = w >> 16;
    int n = w & (Nn - 1);

    // fused: zero wz (one float2 per thread)
    reinterpret_cast<float2*>(g_wz)[w] = make_float2(0.f, 0.f);
    // fused: zero acch (8 coalesced uint4 per thread = 64MB total)
    {
        uint4* a4 = reinterpret_cast<uint4*>(g_acch);
        uint4 z = make_uint4(0u, 0u, 0u, 0u);
#pragma unroll
        for (int k = 0; k < 8; k++) a4[(size_t)k * (BV * Nn) + w] = z;
    }

    float gx = (float)(n & (Ww - 1));
    float gy = (float)(n >> 8);

    float d = __ldcs(&depths[w]);    // read-once
    const float* M = &g_mats[bv * 64];

    // Exact fp32 reference chain: xyp = K*(dstRT*(srcRTinv*(Kinv*proj)))
    float pr[4] = {__fmul_rn(gx, d), __fmul_rn(gy, d), d, 1.f};
    float cam[4], wld[4], c2[4], xyp[4];
    mv4((const float4*)(M + 0),  pr,  cam);
    mv4((const float4*)(M + 16), cam, wld);
    mv4((const float4*)(M + 32), wld, c2);
    mv4((const float4*)(M + 48), c2,  xyp);

    float Z = xyp[2];
    float zeps = __fadd_rn(Z, EPSF);
    float x = __fdiv_rn(xyp[0], zeps);     // reference: xyp0 / (z + eps)
    float y = __fdiv_rn(xyp[1], zeps);
    float invz = __frcp_rn(zeps);          // reference: 1.0 / (z + eps)
    g_xyz[w] = make_float4(x, y, invz, Z);
}

// ---------------- phase A: quadrant 4x4 grid, quarter-warp per tap, fp16 --------
// lane = qb*8 + sl: qb (0..3) = grid column, sl (0..7) = channel octet.
// Slot t = 4*i + qb -> jx = qb, jy = i: per-lane ddx^2 hoists out of the loop.
template <int QX, int QY, bool CHECK>
__device__ __forceinline__ void do_taps(float fx, float fy, float invz,
                                        __half* accp,
                                        __half2 h0, __half2 h1, __half2 h2, __half2 h3,
                                        int qb, float px0, float py0) {
    const float nhiz = __fmul_rn(invz, -0.5f);   // exact
    const int IDX0 = QX ? -1 : -2;
    const int IDY0 = QY ? -1 : -2;
    const int cdx = qb + IDX0;                   // loop-invariant column
    const float dxf = (float)cdx;
    const float ddx = dxf + fx;
    const float ddx2e = __fmaf_rn(ddx, ddx, EPSF);
    bool pxok = true;
    if (CHECK) {
        float px = px0 + dxf;
        pxok = (px >= 0.f) && (px < (float)Ww);
    }
#pragma unroll
    for (int i = 0; i < 4; i++) {
        float dyf = (float)(i + IDY0);
        float ddy = dyf + fy;
        float s2 = __fmaf_rn(ddy, ddy, ddx2e);
        float dist;
        asm("sqrt.approx.f32 %0, %1;" : "=f"(dist) : "f"(s2));
        // ws = (1 - dist/2) * invz, fused; sign(ws) == sign(1 - dist/2) since invz>0
        float ws = __fmaf_rn(dist, nhiz, invz);
        bool live = ws > 0.f;
        if (CHECK) {
            float py = py0 + dyf;
            live = live && pxok && (py >= 0.f) && (py < (float)Hh);
        }
        if (live) {
            __half2 wh = __float2half2_rn(ws);
            __half2 a0 = __hmul2(wh, h0);
            __half2 a1 = __hmul2(wh, h1);
            __half2 a2 = __hmul2(wh, h2);
            __half2 a3 = __hmul2(wh, h3);
            int off = (i + IDY0) * 256 + cdx;
            __half* p = accp + ((long)off << 6);
            asm volatile("red.global.add.noftz.v4.f16x2 [%0], {%1,%2,%3,%4};" ::
                         "l"(p),
                         "r"(*reinterpret_cast<const unsigned*>(&a0)),
                         "r"(*reinterpret_cast<const unsigned*>(&a1)),
                         "r"(*reinterpret_cast<const unsigned*>(&a2)),
                         "r"(*reinterpret_cast<const unsigned*>(&a3)) : "memory");
        }
    }
}

// ------- splat (fused transpose): block = 64 px, smem fp16 tile, warp = 8 px -----
// tile layout: pixel row = 64 halves (128B). Channel octet oct (8 halves, 16B)
// stored at slot oct^(px&7) -> fill stores and splat reads are conflict-light.
__global__ void __launch_bounds__(256, 8) splat_kernel(const float* __restrict__ feats) {
    __shared__ __half tile[64 * 64];    // 8KB
    int tid = threadIdx.x;
    int blk = blockIdx.x;               // [0, BV*Nn/64)
    int bv = blk >> 10;                 // Nn/64 = 1024 blocks per bv
    int n0 = (blk & 1023) * 64;

    // fill: feats[bv][c][n0+px] (fp32, coalesced 256B per channel row) -> fp16 tile
    {
        const float* fb = feats + (size_t)bv * Cc * Nn + n0;
        int px = tid & 63;
        int grp = tid >> 6;             // 0..3
#pragma unroll
        for (int it = 0; it < 4; it++) {
            int cq = it * 4 + grp;      // 4-channel group 0..15
            int c = cq * 4;
            float v0 = __ldcs(&fb[(size_t)(c + 0) * Nn + px]);
            float v1 = __ldcs(&fb[(size_t)(c + 1) * Nn + px]);
            float v2 = __ldcs(&fb[(size_t)(c + 2) * Nn + px]);
            float v3 = __ldcs(&fb[(size_t)(c + 3) * Nn + px]);
            __half2 p0 = __floats2half2_rn(v0, v1);
            __half2 p1 = __floats2half2_rn(v2, v3);
            int oct = cq >> 1, k = cq & 1;
            int soct = oct ^ (px & 7);
            uint2 u;
            u.x = *reinterpret_cast<const unsigned*>(&p0);
            u.y = *reinterpret_cast<const unsigned*>(&p1);
            *reinterpret_cast<uint2*>(&tile[px * 64 + soct * 8 + k * 4]) = u;
        }
    }
    __syncthreads();

    int lane = tid & 31;
    int wid = tid >> 5;
    int qb = lane >> 3;          // grid column 0..3
    int sl = lane & 7;           // channel octet
    __half* accbase = g_acch + ((long)bv << 22);
    float* wzbase = g_wz + ((long)bv << 17);

#pragma unroll 1
    for (int pp = 0; pp < 8; pp++) {
        int p = wid * 8 + pp;
        int w = (bv << 16) + n0 + p;

        float4 pj = __ldcs(&g_xyz[w]);   // warp-uniform broadcast
        float Z = pj.w;
        if (!(Z > EPSF)) continue;       // warp-uniform; ref adds w=0 -> no-op
        float x = pj.x, y = pj.y, invz = pj.z;
        float px0 = rintf(x);            // matches jnp.round (half-to-even)
        float py0 = rintf(y);

        float fx = px0 - x;              // feeds approx dist only
        float fy = py0 - y;
        long idx_base = (long)((int)py0) * Ww + (int)px0;

        bool qx = (fx <= 0.f);           // cx >= 0
        bool qy = (fy <= 0.f);
        float nhiz = __fmul_rn(invz, -0.5f);
        bool interior = (px0 >= 2.f) && (px0 <= (float)(Ww - 3)) &&
                        (py0 >= 2.f) && (py0 <= (float)(Hh - 3));

        // ---- phase B: one warp-wide v2 fp32 RED covers the 16-slot grid.
        if (lane < 16) {
            int iqx0 = qx ? -1 : -2;
            int iqy0 = qy ? -1 : -2;
            int jx = lane & 3, jy = lane >> 2;
            float dxf = (float)(jx + iqx0);
            float dyf = (float)(jy + iqy0);
            int offt = (jy + iqy0) * 256 + jx + iqx0;
            float ddx = dxf + fx;
            float ddy = dyf + fy;
            float s2 = __fmaf_rn(ddx, ddx, __fmaf_rn(ddy, ddy, EPSF));
            float dist;
            asm("sqrt.approx.f32 %0, %1;" : "=f"(dist) : "f"(s2));
            float ws = __fmaf_rn(dist, nhiz, invz);   // identical value to phase A
            bool live = ws > 0.f;
            if (!interior) {
                float px = px0 + dxf;
                float py = py0 + dyf;
                live = live && (px >= 0.f) && (px < (float)Ww) &&
                               (py >= 0.f) && (py < (float)Hh);
            }
            if (live) {
                float* q = wzbase + ((idx_base + offt) << 1);
                asm volatile("red.global.add.v2.f32 [%0], {%1,%2};" ::
                             "l"(q), "f"(ws), "f"(__fmul_rn(ws, Z)) : "memory");
            }
        }

        // ---- phase A: quarter-warp per tap; lane reads its channel octet from smem.
        int soct = sl ^ (p & 7);
        const uint4 fv = *reinterpret_cast<const uint4*>(&tile[p * 64 + soct * 8]);
        __half2 h0 = *reinterpret_cast<const __half2*>(&fv.x);
        __half2 h1 = *reinterpret_cast<const __half2*>(&fv.y);
        __half2 h2 = *reinterpret_cast<const __half2*>(&fv.z);
        __half2 h3 = *reinterpret_cast<const __half2*>(&fv.w);
        __half* accp = accbase + (idx_base << 6) + 8 * sl;

        if (interior) {
            if (qx) { if (qy) do_taps<1,1,false>(fx,fy,invz,accp,h0,h1,h2,h3,qb,px0,py0);
                      else    do_taps<1,0,false>(fx,fy,invz,accp,h0,h1,h2,h3,qb,px0,py0); }
            else    { if (qy) do_taps<0,1,false>(fx,fy,invz,accp,h0,h1,h2,h3,qb,px0,py0);
                      else    do_taps<0,0,false>(fx,fy,invz,accp,h0,h1,h2,h3,qb,px0,py0); }
        } else {
            if (qx) { if (qy) do_taps<1,1,true>(fx,fy,invz,accp,h0,h1,h2,h3,qb,px0,py0);
                      else    do_taps<1,0,true>(fx,fy,invz,accp,h0,h1,h2,h3,qb,px0,py0); }
            else    { if (qy) do_taps<0,1,true>(fx,fy,invz,accp,h0,h1,h2,h3,qb,px0,py0);
                      else    do_taps<0,0,true>(fx,fy,invz,accp,h0,h1,h2,h3,qb,px0,py0); }
        }
    }
}

// ---------------- normalize: 64-px tiles, fp16 acc read, rcp+mul, .cs out --------
__global__ void __launch_bounds__(256) normalize_kernel(float* __restrict__ out) {
    __shared__ float tile[64][65];   // [channel][pixel]
    __shared__ float rws[64];
    __shared__ float zss[64];
    int bv = blockIdx.y;
    int n0 = blockIdx.x * 64;
    int tid = threadIdx.x;

    const uint4* acc16 = reinterpret_cast<const uint4*>(
        g_acch + (((size_t)bv * Nn + n0) << 6));
#pragma unroll
    for (int r = 0; r < 2; r++) {
        int idx = r * 256 + tid;     // [0, 512): 8 uint4 per pixel
        int p = idx >> 3;            // pixel 0..63
        int q8 = idx & 7;            // channel octet
        uint4 v = acc16[idx];
        const __half2* hp = reinterpret_cast<const __half2*>(&v);
#pragma unroll
        for (int k = 0; k < 4; k++) {
            float2 f2 = __half22float2(hp[k]);
            tile[8 * q8 + 2 * k + 0][p] = f2.x;
            tile[8 * q8 + 2 * k + 1][p] = f2.y;
        }
    }
    if (tid < 64) {
        float2 wzv = reinterpret_cast<const float2*>(g_wz)[(size_t)bv * Nn + n0 + tid];
        rws[tid] = __frcp_rn(__fadd_rn(wzv.x, EPSF));  // rcp+mul vs div: <=2ulp
        zss[tid] = wzv.y;
    }
    __syncthreads();

    float* ob = out + (size_t)bv * (Cc + 1) * Nn + n0;
#pragma unroll
    for (int r = 0; r < 4; r++) {
        int idx = r * 256 + tid;
        int c = idx >> 4;            // channel 0..63
        int j = idx & 15;            // pixel quad
        float4 o;
        o.x = __fmul_rn(tile[c][4 * j + 0], rws[4 * j + 0]);
        o.y = __fmul_rn(tile[c][4 * j + 1], rws[4 * j + 1]);
        o.z = __fmul_rn(tile[c][4 * j + 2], rws[4 * j + 2]);
        o.w = __fmul_rn(tile[c][4 * j + 3], rws[4 * j + 3]);
        __stcs(reinterpret_cast<float4*>(ob + (size_t)c * Nn) + j, o);
    }
    if (tid < 16) {
        int j = tid;
        float4 o;
        o.x = __fmul_rn(zss[4 * j + 0], rws[4 * j + 0]);
        o.y = __fmul_rn(zss[4 * j + 1], rws[4 * j + 1]);
        o.z = __fmul_rn(zss[4 * j + 2], rws[4 * j + 2]);
        o.w = __fmul_rn(zss[4 * j + 3], rws[4 * j + 3]);
        __stcs(reinterpret_cast<float4*>(ob + (size_t)Cc * Nn) + j, o);
    }
}

// ---------------- launch: serial; transpose fused into splat ---------------------
extern "C" void kernel_launch(void* const* d_in, const int* in_sizes, int n_in,
                              void* d_out, int out_size) {
    const float* feats    = (const float*)d_in[0];
    const float* depths   = (const float*)d_in[1];
    const float* K        = (const float*)d_in[2];
    const float* srcRTinv = (const float*)d_in[4];
    const float* dstRT    = (const float*)d_in[5];
    float* out = (float*)d_out;

    build_mats_kernel<<<1, 32>>>(K, srcRTinv, dstRT);
    proj_kernel<<<(BV * Nn) / 256, 256>>>(depths);       // + zeroes g_wz, g_acch
    splat_kernel<<<(BV * Nn) / 64, 256>>>(feats);        // fused transpose
    normalize_kernel<<<dim3(Nn / 64, BV), 256>>>(out);
}

// round 17
// speedup vs baseline: 1.1767x; 1.0098x over previous
#include <cuda_runtime.h>
#include <cuda_fp16.h>
#include <cstdint>

#define Bb 2
#define Vv 4
#define Cc 64
#define Hh 256
#define Ww 256
#define Nn (Hh * Ww)       // 65536
#define BV (Bb * Vv)       // 8
#define EPSF 1e-8f

// ---------------- scratch (device globals: allocation-free per harness rules) ----
__device__ __align__(16) __half g_acch[(size_t)BV * Nn * Cc];    // accumulator fp16  64MB
__device__ float g_wz[(size_t)BV * Nn * 2];       // per-target (wsum, wz) fp32        4MB
// per-bv matrices (exact fp32): [Kinv(16), srcRTinv(16), dstRT(16), K(16)]
__device__ float g_mats[BV * 64];

// Exact fp32 4x4 matvec, fma chain ascending j (matches XLA dot lowering order).
__device__ __forceinline__ void mv4(const float4* __restrict__ M,
                                    const float v[4], float o[4]) {
#pragma unroll
    for (int r = 0; r < 4; r++) {
        float4 m = __ldg(&M[r]);
        float s = __fmul_rn(m.x, v[0]);
        s = __fmaf_rn(m.y, v[1], s);
        s = __fmaf_rn(m.z, v[2], s);
        s = __fmaf_rn(m.w, v[3], s);
        o[r] = s;
    }
}

// ---------------- 4x4 inverse (Gauss-Jordan, partial pivot) ---------------------
__device__ void inv4(const float* a, float* o) {
    float m[4][8];
    for (int r = 0; r < 4; r++)
        for (int c = 0; c < 4; c++) {
            m[r][c] = a[r * 4 + c];
            m[r][4 + c] = (r == c) ? 1.f : 0.f;
        }
    for (int col = 0; col < 4; col++) {
        int piv = col;
        for (int r = col + 1; r < 4; r++)
            if (fabsf(m[r][col]) > fabsf(m[piv][col])) piv = r;
        if (piv != col)
            for (int c = 0; c < 8; c++) { float t = m[col][c]; m[col][c] = m[piv][c]; m[piv][c] = t; }
        float s = __fdiv_rn(1.f, m[col][col]);
        for (int c = 0; c < 8; c++) m[col][c] = __fmul_rn(m[col][c], s);
        for (int r = 0; r < 4; r++) {
            if (r == col) continue;
            float f = m[r][col];
            for (int c = 0; c < 8; c++) m[r][c] = __fmaf_rn(-f, m[col][c], m[r][c]);
        }
    }
    for (int r = 0; r < 4; r++)
        for (int c = 0; c < 4; c++) o[r * 4 + c] = m[r][4 + c];
}

__global__ void build_mats_kernel(const float* __restrict__ K,
                                  const float* __restrict__ srcRTinv,
                                  const float* __restrict__ dstRT) {
    int bv = threadIdx.x;
    if (bv >= BV) return;
    int b = bv / Vv;
    float Kb[16], Ki[16];
    for (int i = 0; i < 16; i++) Kb[i] = K[b * 16 + i];
    inv4(Kb, Ki);
    float* out = &g_mats[bv * 64];
    for (int i = 0; i < 16; i++) {
        out[i]      = Ki[i];
        out[16 + i] = srcRTinv[bv * 16 + i];
        out[32 + i] = dstRT[b * 16 + i];   // dst_RTs is (B,1,4,4)
        out[48 + i] = Kb[i];
    }
}

// ---------------- zero accumulators (grid-stride, wide stores) -------------------
__global__ void __launch_bounds__(256) zero_kernel() {
    const size_t stride = (size_t)gridDim.x * blockDim.x;
    size_t i = (size_t)blockIdx.x * blockDim.x + threadIdx.x;
    uint4 z = make_uint4(0u, 0u, 0u, 0u);
    uint4* a4 = reinterpret_cast<uint4*>(g_acch);
    const size_t na = (size_t)BV * Nn * Cc * 2 / 16;   // 4M uint4
    for (size_t j = i; j < na; j += stride) a4[j] = z;
    uint4* w4 = reinterpret_cast<uint4*>(g_wz);
    const size_t nw = (size_t)BV * Nn * 2 * 4 / 16;    // 256K uint4
    for (size_t j = i; j < nw; j += stride) w4[j] = z;
}

// ---------------- phase A: quadrant 4x4 grid, quarter-warp per tap, fp16 --------
// lane = qb*8 + sl: qb (0..3) = grid column, sl (0..7) = channel octet.
// Slot t = 4*i + qb -> jx = qb, jy = i: per-lane ddx^2 hoists out of the loop.
template <int QX, int QY, bool CHECK>
__device__ __forceinline__ void do_taps(float fx, float fy, float invz,
                                        __half* accp,
                                        __half2 h0, __half2 h1, __half2 h2, __half2 h3,
                                        int qb, float px0, float py0) {
    const float nhiz = __fmul_rn(invz, -0.5f);   // exact
    const int IDX0 = QX ? -1 : -2;
    const int IDY0 = QY ? -1 : -2;
    const int cdx = qb + IDX0;                   // loop-invariant column
    const float dxf = (float)cdx;
    const float ddx = dxf + fx;
    const float ddx2e = __fmaf_rn(ddx, ddx, EPSF);
    bool pxok = true;
    if (CHECK) {
        float px = px0 + dxf;
        pxok = (px >= 0.f) && (px < (float)Ww);
    }
#pragma unroll
    for (int i = 0; i < 4; i++) {
        float dyf = (float)(i + IDY0);
        float ddy = dyf + fy;
        float s2 = __fmaf_rn(ddy, ddy, ddx2e);
        float dist;
        asm("sqrt.approx.f32 %0, %1;" : "=f"(dist) : "f"(s2));
        // ws = (1 - dist/2) * invz, fused; sign(ws) == sign(1 - dist/2) since invz>0
        float ws = __fmaf_rn(dist, nhiz, invz);
        bool live = ws > 0.f;
        if (CHECK) {
            float py = py0 + dyf;
            live = live && pxok && (py >= 0.f) && (py < (float)Hh);
        }
        if (live) {
            __half2 wh = __float2half2_rn(ws);
            __half2 a0 = __hmul2(wh, h0);
            __half2 a1 = __hmul2(wh, h1);
            __half2 a2 = __hmul2(wh, h2);
            __half2 a3 = __hmul2(wh, h3);
            int off = (i + IDY0) * 256 + cdx;
            __half* p = accp + ((long)off << 6);
            asm volatile("red.global.add.noftz.v4.f16x2 [%0], {%1,%2,%3,%4};" ::
                         "l"(p),
                         "r"(*reinterpret_cast<const unsigned*>(&a0)),
                         "r"(*reinterpret_cast<const unsigned*>(&a1)),
                         "r"(*reinterpret_cast<const unsigned*>(&a2)),
                         "r"(*reinterpret_cast<const unsigned*>(&a3)) : "memory");
        }
    }
}

// ------- splat (fused transpose + projection): block = 64 px, warp = 8 px --------
// tile layout: pixel row = 64 halves (128B). Channel octet oct (8 halves, 16B)
// stored at slot oct^(px&7) -> fill stores and splat reads are conflict-light.
__global__ void __launch_bounds__(256, 8) splat_kernel(const float* __restrict__ feats,
                                                       const float* __restrict__ depths) {
    __shared__ __half tile[64 * 64];    // 8KB
    int tid = threadIdx.x;
    int blk = blockIdx.x;               // [0, BV*Nn/64)
    int bv = blk >> 10;                 // Nn/64 = 1024 blocks per bv
    int n0 = (blk & 1023) * 64;
    int lane = tid & 31;
    int wid = tid >> 5;

    // ---- fused projection: every lane computes the exact fp32 chain for pixel
    // wid*8 + (lane&7) (4x redundant across the warp; broadcast later via shfl).
    float xr, yr, invzr, Zr;
    {
        int p = wid * 8 + (lane & 7);
        int n = n0 + p;
        int w = (bv << 16) + n;
        float gx = (float)(n & (Ww - 1));
        float gy = (float)(n >> 8);
        float d = __ldcs(&depths[w]);
        const float* M = &g_mats[bv * 64];
        // Exact fp32 reference chain: xyp = K*(dstRT*(srcRTinv*(Kinv*proj)))
        float pr[4] = {__fmul_rn(gx, d), __fmul_rn(gy, d), d, 1.f};
        float cam[4], wld[4], c2[4], xyp[4];
        mv4((const float4*)(M + 0),  pr,  cam);
        mv4((const float4*)(M + 16), cam, wld);
        mv4((const float4*)(M + 32), wld, c2);
        mv4((const float4*)(M + 48), c2,  xyp);
        Zr = xyp[2];
        float zeps = __fadd_rn(Zr, EPSF);
        xr = __fdiv_rn(xyp[0], zeps);     // reference: xyp0 / (z + eps)
        yr = __fdiv_rn(xyp[1], zeps);
        invzr = __frcp_rn(zeps);          // reference: 1.0 / (z + eps)
    }

    // ---- fill: feats[bv][c][n0+px] (fp32, coalesced) -> fp16 smem tile
    {
        const float* fb = feats + (size_t)bv * Cc * Nn + n0;
        int px = tid & 63;
        int grp = tid >> 6;             // 0..3
#pragma unroll
        for (int it = 0; it < 4; it++) {
            int cq = it * 4 + grp;      // 4-channel group 0..15
            int c = cq * 4;
            float v0 = __ldcs(&fb[(size_t)(c + 0) * Nn + px]);
            float v1 = __ldcs(&fb[(size_t)(c + 1) * Nn + px]);
            float v2 = __ldcs(&fb[(size_t)(c + 2) * Nn + px]);
            float v3 = __ldcs(&fb[(size_t)(c + 3) * Nn + px]);
            __half2 p0 = __floats2half2_rn(v0, v1);
            __half2 p1 = __floats2half2_rn(v2, v3);
            int oct = cq >> 1, k = cq & 1;
            int soct = oct ^ (px & 7);
            uint2 u;
            u.x = *reinterpret_cast<const unsigned*>(&p0);
            u.y = *reinterpret_cast<const unsigned*>(&p1);
            *reinterpret_cast<uint2*>(&tile[px * 64 + soct * 8 + k * 4]) = u;
        }
    }
    __syncthreads();

    int qb = lane >> 3;          // grid column 0..3
    int sl = lane & 7;           // channel octet
    __half* accbase = g_acch + ((long)bv << 22);
    float* wzbase = g_wz + ((long)bv << 17);

#pragma unroll 1
    for (int pp = 0; pp < 8; pp++) {
        int p = wid * 8 + pp;

        // broadcast pixel pp's projection from the lane that computed it
        float x    = __shfl_sync(0xffffffffu, xr,    pp, 8);
        float y    = __shfl_sync(0xffffffffu, yr,    pp, 8);
        float invz = __shfl_sync(0xffffffffu, invzr, pp, 8);
        float Z    = __shfl_sync(0xffffffffu, Zr,    pp, 8);
        if (!(Z > EPSF)) continue;       // warp-uniform; ref adds w=0 -> no-op

        float px0 = rintf(x);            // matches jnp.round (half-to-even)
        float py0 = rintf(y);
        float fx = px0 - x;              // feeds approx dist only
        float fy = py0 - y;
        long idx_base = (long)((int)py0) * Ww + (int)px0;

        bool qx = (fx <= 0.f);           // cx >= 0
        bool qy = (fy <= 0.f);
        float nhiz = __fmul_rn(invz, -0.5f);
        bool interior = (px0 >= 2.f) && (px0 <= (float)(Ww - 3)) &&
                        (py0 >= 2.f) && (py0 <= (float)(Hh - 3));

        // ---- phase B: one warp-wide v2 fp32 RED covers the 16-slot grid.
        if (lane < 16) {
            int iqx0 = qx ? -1 : -2;
            int iqy0 = qy ? -1 : -2;
            int jx = lane & 3, jy = lane >> 2;
            float dxf = (float)(jx + iqx0);
            float dyf = (float)(jy + iqy0);
            int offt = (jy + iqy0) * 256 + jx + iqx0;
            float ddx = dxf + fx;
            float ddy = dyf + fy;
            float s2 = __fmaf_rn(ddx, ddx, __fmaf_rn(ddy, ddy, EPSF));
            float dist;
            asm("sqrt.approx.f32 %0, %1;" : "=f"(dist) : "f"(s2));
            float ws = __fmaf_rn(dist, nhiz, invz);   // identical value to phase A
            bool live = ws > 0.f;
            if (!interior) {
                float px = px0 + dxf;
                float py = py0 + dyf;
                live = live && (px >= 0.f) && (px < (float)Ww) &&
                               (py >= 0.f) && (py < (float)Hh);
            }
            if (live) {
                float* q = wzbase + ((idx_base + offt) << 1);
                asm volatile("red.global.add.v2.f32 [%0], {%1,%2};" ::
                             "l"(q), "f"(ws), "f"(__fmul_rn(ws, Z)) : "memory");
            }
        }

        // ---- phase A: quarter-warp per tap; lane reads its channel octet from smem.
        int soct = sl ^ (p & 7);
        const uint4 fv = *reinterpret_cast<const uint4*>(&tile[p * 64 + soct * 8]);
        __half2 h0 = *reinterpret_cast<const __half2*>(&fv.x);
        __half2 h1 = *reinterpret_cast<const __half2*>(&fv.y);
        __half2 h2 = *reinterpret_cast<const __half2*>(&fv.z);
        __half2 h3 = *reinterpret_cast<const __half2*>(&fv.w);
        __half* accp = accbase + (idx_base << 6) + 8 * sl;

        if (interior) {
            if (qx) { if (qy) do_taps<1,1,false>(fx,fy,invz,accp,h0,h1,h2,h3,qb,px0,py0);
                      else    do_taps<1,0,false>(fx,fy,invz,accp,h0,h1,h2,h3,qb,px0,py0); }
            else    { if (qy) do_taps<0,1,false>(fx,fy,invz,accp,h0,h1,h2,h3,qb,px0,py0);
                      else    do_taps<0,0,false>(fx,fy,invz,accp,h0,h1,h2,h3,qb,px0,py0); }
        } else {
            if (qx) { if (qy) do_taps<1,1,true>(fx,fy,invz,accp,h0,h1,h2,h3,qb,px0,py0);
                      else    do_taps<1,0,true>(fx,fy,invz,accp,h0,h1,h2,h3,qb,px0,py0); }
            else    { if (qy) do_taps<0,1,true>(fx,fy,invz,accp,h0,h1,h2,h3,qb,px0,py0);
                      else    do_taps<0,0,true>(fx,fy,invz,accp,h0,h1,h2,h3,qb,px0,py0); }
        }
    }
}

// ---------------- normalize: 64-px tiles, fp16 acc read, rcp+mul, .cs out --------
__global__ void __launch_bounds__(256) normalize_kernel(float* __restrict__ out) {
    __shared__ float tile[64][65];   // [channel][pixel]
    __shared__ float rws[64];
    __shared__ float zss[64];
    int bv = blockIdx.y;
    int n0 = blockIdx.x * 64;
    int tid = threadIdx.x;

    const uint4* acc16 = reinterpret_cast<const uint4*>(
        g_acch + (((size_t)bv * Nn + n0) << 6));
#pragma unroll
    for (int r = 0; r < 2; r++) {
        int idx = r * 256 + tid;     // [0, 512): 8 uint4 per pixel
        int p = idx >> 3;            // pixel 0..63
        int q8 = idx & 7;            // channel octet
        uint4 v = acc16[idx];
        const __half2* hp = reinterpret_cast<const __half2*>(&v);
#pragma unroll
        for (int k = 0; k < 4; k++) {
            float2 f2 = __half22float2(hp[k]);
            tile[8 * q8 + 2 * k + 0][p] = f2.x;
            tile[8 * q8 + 2 * k + 1][p] = f2.y;
        }
    }
    if (tid < 64) {
        float2 wzv = reinterpret_cast<const float2*>(g_wz)[(size_t)bv * Nn + n0 + tid];
        rws[tid] = __frcp_rn(__fadd_rn(wzv.x, EPSF));  // rcp+mul vs div: <=2ulp
        zss[tid] = wzv.y;
    }
    __syncthreads();

    float* ob = out + (size_t)bv * (Cc + 1) * Nn + n0;
#pragma unroll
    for (int r = 0; r < 4; r++) {
        int idx = r * 256 + tid;
        int c = idx >> 4;            // channel 0..63
        int j = idx & 15;            // pixel quad
        float4 o;
        o.x = __fmul_rn(tile[c][4 * j + 0], rws[4 * j + 0]);
        o.y = __fmul_rn(tile[c][4 * j + 1], rws[4 * j + 1]);
        o.z = __fmul_rn(tile[c][4 * j + 2], rws[4 * j + 2]);
        o.w = __fmul_rn(tile[c][4 * j + 3], rws[4 * j + 3]);
        __stcs(reinterpret_cast<float4*>(ob + (size_t)c * Nn) + j, o);
    }
    if (tid < 16) {
        int j = tid;
        float4 o;
        o.x = __fmul_rn(zss[4 * j + 0], rws[4 * j + 0]);
        o.y = __fmul_rn(zss[4 * j + 1], rws[4 * j + 1]);
        o.z = __fmul_rn(zss[4 * j + 2], rws[4 * j + 2]);
        o.w = __fmul_rn(zss[4 * j + 3], rws[4 * j + 3]);
        __stcs(reinterpret_cast<float4*>(ob + (size_t)Cc * Nn) + j, o);
    }
}

// ---------------- launch: serial; projection + transpose fused into splat --------
extern "C" void kernel_launch(void* const* d_in, const int* in_sizes, int n_in,
                              void* d_out, int out_size) {
    const float* feats    = (const float*)d_in[0];
    const float* depths   = (const float*)d_in[1];
    const float* K        = (const float*)d_in[2];
    const float* srcRTinv = (const float*)d_in[4];
    const float* dstRT    = (const float*)d_in[5];
    float* out = (float*)d_out;

    build_mats_kernel<<<1, 32>>>(K, srcRTinv, dstRT);
    zero_kernel<<<4096, 256>>>();
    splat_kernel<<<(BV * Nn) / 64, 256>>>(feats, depths);
    normalize_kernel<<<dim3(Nn / 64, BV), 256>>>(out);
}